// round 2
// baseline (speedup 1.0000x reference)
#include <cuda_runtime.h>
#include <math.h>

#define BB 4
#define SS 512
#define HH 768
#define DD 24
#define MM 96
#define RR (BB*SS)      // 2048
#define KX (3*HH)       // 2304

// ---------------- scratch (device globals; no allocation allowed) ----------------
__device__ __align__(16) float g_Zj[BB*SS*DD];
__device__ __align__(16) float g_Zi[BB*SS*DD];
__device__ __align__(16) float g_probs[BB*SS*SS];     // 4 MB
__device__ __align__(16) float g_ctx[BB*SS*HH];       // 6 MB
__device__ __align__(16) float g_X[RR*KX];            // 18.9 MB
__device__ __align__(16) float g_mhid[RR*HH];         // 6 MB

// ---------------- K1: Z projections ----------------
// grid (RR/8, 2), block (24, 8)
__global__ void proj_kernel(const float* __restrict__ Hj, const float* __restrict__ Hi,
                            const float* __restrict__ Wpj, const float* __restrict__ Wpi)
{
    int which = blockIdx.y;
    const float* Hsrc = which ? Hi : Hj;
    const float* W    = which ? Wpi : Wpj;
    float* Z          = which ? g_Zi : g_Zj;
    int row = blockIdx.x * 8 + threadIdx.y;
    int col = threadIdx.x;
    const float* h = Hsrc + (size_t)row * HH;
    float acc = 0.f;
    #pragma unroll 8
    for (int k = 0; k < HH; ++k)
        acc = fmaf(h[k], W[k*DD + col], acc);
    Z[row*DD + col] = acc;
}

// ---------------- K2: fused pairwise scores + softmax -> probs ----------------
// grid (SS, BB), block 256, dyn smem 70240 B
__global__ void __launch_bounds__(256) pairwise_kernel(
        const float* __restrict__ Ws1, const float* __restrict__ bs1,
        const float* __restrict__ ws2, const float* __restrict__ bs2p,
        const int*   __restrict__ mask)
{
    extern __shared__ float smem[];
    float2* sPair  = (float2*)smem;                   // DD*MM float2  (4608 floats)
    float*  sZi    = smem + 2*DD*MM;                  // SS*DD         (12288)
    float*  sLog   = sZi + SS*DD;                     // SS            (512)
    float*  sBias  = sLog + SS;                       // MM            (96)
    float*  sZj    = sBias + MM;                      // DD            (24)
    float*  sRed   = sZj + DD;                        // 32

    int b = blockIdx.y, p = blockIdx.x;
    int tid = threadIdx.x;
    int lane = tid & 31, warp = tid >> 5;

    if (tid < DD) sZj[tid] = g_Zj[((size_t)b*SS + p)*DD + tid];
    __syncthreads();

    // Zi tile (whole batch row block): vectorized copy
    {
        const float4* src = (const float4*)(g_Zi + (size_t)b*SS*DD);
        float4* dst = (float4*)sZi;
        for (int i = tid; i < SS*DD/4; i += 256) dst[i] = src[i];
    }
    // Per-p combined weights: Wcomb[d,m] = W1i + Zj[p,d]*W1h ; pack with W1d as float2
    for (int idx = tid; idx < DD*MM; idx += 256) {
        int d = idx / MM, m = idx - d*MM;
        float w1i = Ws1[(DD   + d)*MM + m];
        float w1h = Ws1[(2*DD + d)*MM + m];
        float w1d = Ws1[(3*DD + d)*MM + m];
        sPair[idx] = make_float2(fmaf(sZj[d], w1h, w1i), w1d);
    }
    // Per-p bias: tj[p,m] + bs1[m]
    if (tid < MM) {
        float acc = bs1[tid];
        #pragma unroll
        for (int d = 0; d < DD; ++d)
            acc = fmaf(sZj[d], Ws1[d*MM + tid], acc);
        sBias[tid] = acc;
    }
    __syncthreads();

    float zj[DD];
    #pragma unroll
    for (int d = 0; d < DD; ++d) zj[d] = sZj[d];

    int m0 = lane, m1 = lane + 32, m2 = lane + 64;
    float wsa = ws2[m0], wsb = ws2[m1], wsc = ws2[m2];
    float bi0 = sBias[m0], bi1 = sBias[m1], bi2 = sBias[m2];
    float bsc = bs2p[0];
    const int* mrow = mask + b*SS;

    // each warp handles 4 q per iteration; 8 warps * 4 q * 16 iters = 512
    for (int it = 0; it < SS/32; ++it) {
        int qb = it*32 + warp*4;
        float a[4][3];
        #pragma unroll
        for (int qq = 0; qq < 4; ++qq) { a[qq][0]=bi0; a[qq][1]=bi1; a[qq][2]=bi2; }

        #pragma unroll
        for (int d = 0; d < DD; ++d) {
            float z0 = sZi[(qb+0)*DD + d];
            float z1 = sZi[(qb+1)*DD + d];
            float z2 = sZi[(qb+2)*DD + d];
            float z3 = sZi[(qb+3)*DD + d];
            float zjd = zj[d];
            float f0 = fabsf(zjd - z0), f1 = fabsf(zjd - z1);
            float f2 = fabsf(zjd - z2), f3 = fabsf(zjd - z3);
            float2 w0 = sPair[d*MM + m0];
            float2 w1 = sPair[d*MM + m1];
            float2 w2 = sPair[d*MM + m2];
            a[0][0] = fmaf(z0, w0.x, fmaf(f0, w0.y, a[0][0]));
            a[0][1] = fmaf(z0, w1.x, fmaf(f0, w1.y, a[0][1]));
            a[0][2] = fmaf(z0, w2.x, fmaf(f0, w2.y, a[0][2]));
            a[1][0] = fmaf(z1, w0.x, fmaf(f1, w0.y, a[1][0]));
            a[1][1] = fmaf(z1, w1.x, fmaf(f1, w1.y, a[1][1]));
            a[1][2] = fmaf(z1, w2.x, fmaf(f1, w2.y, a[1][2]));
            a[2][0] = fmaf(z2, w0.x, fmaf(f2, w0.y, a[2][0]));
            a[2][1] = fmaf(z2, w1.x, fmaf(f2, w1.y, a[2][1]));
            a[2][2] = fmaf(z2, w2.x, fmaf(f2, w2.y, a[2][2]));
            a[3][0] = fmaf(z3, w0.x, fmaf(f3, w0.y, a[3][0]));
            a[3][1] = fmaf(z3, w1.x, fmaf(f3, w1.y, a[3][1]));
            a[3][2] = fmaf(z3, w2.x, fmaf(f3, w2.y, a[3][2]));
        }
        #pragma unroll
        for (int qq = 0; qq < 4; ++qq) {
            float h0 = fmaxf(a[qq][0], 0.f);
            float h1 = fmaxf(a[qq][1], 0.f);
            float h2 = fmaxf(a[qq][2], 0.f);
            float s = h0*wsa + h1*wsb + h2*wsc;
            #pragma unroll
            for (int o = 16; o; o >>= 1) s += __shfl_xor_sync(0xffffffffu, s, o);
            if (lane == 0) {
                float lg = s + bsc;
                if (mrow[qb+qq] == 0) lg = -3.0e38f;
                sLog[qb+qq] = lg;
            }
        }
    }
    __syncthreads();

    // block softmax over 512 logits
    float v = -3.4e38f;
    for (int i = tid; i < SS; i += 256) v = fmaxf(v, sLog[i]);
    #pragma unroll
    for (int o = 16; o; o >>= 1) v = fmaxf(v, __shfl_xor_sync(0xffffffffu, v, o));
    if (lane == 0) sRed[warp] = v;
    __syncthreads();
    float gmax = sRed[0];
    #pragma unroll
    for (int w = 1; w < 8; ++w) gmax = fmaxf(gmax, sRed[w]);
    __syncthreads();

    float ls = 0.f;
    for (int i = tid; i < SS; i += 256) {
        float e = expf(sLog[i] - gmax);
        sLog[i] = e;
        ls += e;
    }
    #pragma unroll
    for (int o = 16; o; o >>= 1) ls += __shfl_xor_sync(0xffffffffu, ls, o);
    if (lane == 0) sRed[warp] = ls;
    __syncthreads();
    float gsum = 0.f;
    #pragma unroll
    for (int w = 0; w < 8; ++w) gsum += sRed[w];
    float inv = 1.f / gsum;

    float* prow = g_probs + ((size_t)b*SS + p)*SS;
    for (int i = tid; i < SS; i += 256) prow[i] = sLog[i] * inv;
}

// ---------------- K_X: build X = [ctx | H_j | ctx*H_j] ----------------
__global__ void build_x_kernel(const float* __restrict__ Hj)
{
    int i = blockIdx.x * blockDim.x + threadIdx.x;
    if (i >= RR*HH) return;
    int r = i / HH, h = i - r*HH;
    float c  = g_ctx[i];
    float hj = Hj[i];
    float* xr = g_X + (size_t)r * KX;
    xr[h]        = c;
    xr[HH + h]   = hj;
    xr[2*HH + h] = c * hj;
}

// ---------------- generic tiled SGEMM: C(MxN) = A(MxK) @ B(KxN), row-major packed ----------------
// MODE 0: plain; MODE 1: relu(acc + bias[col]); MODE 2: alpha*(acc + bias[col])
template<int MODE>
__global__ void __launch_bounds__(256) gemm_tile(
        const float* __restrict__ A, const float* __restrict__ Bm, float* __restrict__ C,
        int K, int N, size_t sA, size_t sB, size_t sC,
        const float* __restrict__ bias, const float* __restrict__ alphap)
{
    A  += (size_t)blockIdx.z * sA;
    Bm += (size_t)blockIdx.z * sB;
    C  += (size_t)blockIdx.z * sC;

    __shared__ float As[16][64];
    __shared__ float Bs[16][64];

    int tid = threadIdx.x;
    int tx = tid & 15, ty = tid >> 4;
    int rowA = tid >> 2, cgA = tid & 3;     // A tile: 64 rows x 16 k
    int rowB = tid >> 4, cgB = tid & 15;    // B tile: 16 k x 64 cols

    const float* Aptr = A + ((size_t)blockIdx.y*64 + rowA)*K + cgA*4;
    const float* Bptr = Bm + (size_t)rowB*N + blockIdx.x*64 + cgB*4;

    float acc[4][4];
    #pragma unroll
    for (int i = 0; i < 4; ++i)
        #pragma unroll
        for (int j = 0; j < 4; ++j) acc[i][j] = 0.f;

    for (int k0 = 0; k0 < K; k0 += 16) {
        float4 av = *(const float4*)(Aptr + k0);
        float4 bv = *(const float4*)(Bptr + (size_t)k0*N);
        As[cgA*4+0][rowA] = av.x;
        As[cgA*4+1][rowA] = av.y;
        As[cgA*4+2][rowA] = av.z;
        As[cgA*4+3][rowA] = av.w;
        *(float4*)&Bs[rowB][cgB*4] = bv;
        __syncthreads();
        #pragma unroll
        for (int kk = 0; kk < 16; ++kk) {
            float4 a = *(const float4*)&As[kk][ty*4];
            float4 bq = *(const float4*)&Bs[kk][tx*4];
            acc[0][0]=fmaf(a.x,bq.x,acc[0][0]); acc[0][1]=fmaf(a.x,bq.y,acc[0][1]);
            acc[0][2]=fmaf(a.x,bq.z,acc[0][2]); acc[0][3]=fmaf(a.x,bq.w,acc[0][3]);
            acc[1][0]=fmaf(a.y,bq.x,acc[1][0]); acc[1][1]=fmaf(a.y,bq.y,acc[1][1]);
            acc[1][2]=fmaf(a.y,bq.z,acc[1][2]); acc[1][3]=fmaf(a.y,bq.w,acc[1][3]);
            acc[2][0]=fmaf(a.z,bq.x,acc[2][0]); acc[2][1]=fmaf(a.z,bq.y,acc[2][1]);
            acc[2][2]=fmaf(a.z,bq.z,acc[2][2]); acc[2][3]=fmaf(a.z,bq.w,acc[2][3]);
            acc[3][0]=fmaf(a.w,bq.x,acc[3][0]); acc[3][1]=fmaf(a.w,bq.y,acc[3][1]);
            acc[3][2]=fmaf(a.w,bq.z,acc[3][2]); acc[3][3]=fmaf(a.w,bq.w,acc[3][3]);
        }
        __syncthreads();
    }

    float al = (MODE == 2) ? *alphap : 1.f;
    int crow = blockIdx.y*64 + ty*4;
    int ccol = blockIdx.x*64 + tx*4;
    float bb[4] = {0.f, 0.f, 0.f, 0.f};
    if (MODE != 0) {
        #pragma unroll
        for (int j = 0; j < 4; ++j) bb[j] = bias[ccol + j];
    }
    #pragma unroll
    for (int i = 0; i < 4; ++i) {
        float4 o;
        float v0 = acc[i][0] + bb[0], v1 = acc[i][1] + bb[1];
        float v2 = acc[i][2] + bb[2], v3 = acc[i][3] + bb[3];
        if (MODE == 1) { v0 = fmaxf(v0,0.f); v1 = fmaxf(v1,0.f); v2 = fmaxf(v2,0.f); v3 = fmaxf(v3,0.f); }
        if (MODE == 2) { v0 *= al; v1 *= al; v2 *= al; v3 *= al; }
        o.x = v0; o.y = v1; o.z = v2; o.w = v3;
        *(float4*)&C[(size_t)(crow + i)*N + ccol] = o;
    }
}

// ---------------- launch ----------------
extern "C" void kernel_launch(void* const* d_in, const int* in_sizes, int n_in,
                              void* d_out, int out_size)
{
    const float* Hj   = (const float*)d_in[0];
    const float* Hi   = (const float*)d_in[1];
    const float* Wpj  = (const float*)d_in[2];
    const float* Wpi  = (const float*)d_in[3];
    const float* Ws1  = (const float*)d_in[4];
    const float* bs1  = (const float*)d_in[5];
    const float* ws2  = (const float*)d_in[6];
    const float* bs2  = (const float*)d_in[7];
    const float* Wv1  = (const float*)d_in[8];
    const float* bv1  = (const float*)d_in[9];
    const float* Wv2  = (const float*)d_in[10];
    const float* bv2  = (const float*)d_in[11];
    const float* alph = (const float*)d_in[12];
    const int*   amask= (const int*)d_in[13];
    float* out = (float*)d_out;

    float *pProbs, *pCtx, *pX, *pMhid;
    cudaGetSymbolAddress((void**)&pProbs, g_probs);
    cudaGetSymbolAddress((void**)&pCtx,   g_ctx);
    cudaGetSymbolAddress((void**)&pX,     g_X);
    cudaGetSymbolAddress((void**)&pMhid,  g_mhid);

    // K1: projections
    proj_kernel<<<dim3(RR/8, 2), dim3(24, 8)>>>(Hj, Hi, Wpj, Wpi);

    // K2: pairwise + softmax
    const size_t smemPW = (size_t)(2*DD*MM + SS*DD + SS + MM + DD + 32) * sizeof(float);
    cudaFuncSetAttribute(pairwise_kernel, cudaFuncAttributeMaxDynamicSharedMemorySize, (int)smemPW);
    pairwise_kernel<<<dim3(SS, BB), 256, smemPW>>>(Ws1, bs1, ws2, bs2, amask);

    // K3: ctx = probs @ H_i   (batched: M=512, K=512, N=768)
    gemm_tile<0><<<dim3(HH/64, SS/64, BB), 256>>>(
        pProbs, Hi, pCtx, SS, HH,
        (size_t)SS*SS, (size_t)SS*HH, (size_t)SS*HH, nullptr, nullptr);

    // K_X: X = [ctx | H_j | ctx*H_j]
    build_x_kernel<<<(RR*HH + 255)/256, 256>>>(Hj);

    // K4: mhid = relu(X @ Wv1 + bv1)  (M=2048, K=2304, N=768)
    gemm_tile<1><<<dim3(HH/64, RR/64, 1), 256>>>(
        pX, Wv1, pMhid, KX, HH, 0, 0, 0, bv1, nullptr);

    // K5: out = alpha * (mhid @ Wv2 + bv2)  (M=2048, K=768, N=768)
    gemm_tile<2><<<dim3(HH/64, RR/64, 1), 256>>>(
        pMhid, Wv2, out, HH, HH, 0, 0, 0, bv2, alph);
}

// round 4
// speedup vs baseline: 1.0318x; 1.0318x over previous
#include <cuda_runtime.h>
#include <math.h>

#define BB 4
#define SS 512
#define HH 768
#define DD 24
#define MM 96
#define RR (BB*SS)      // 2048
#define KX (3*HH)       // 2304
#define ZST 514         // padded transpose stride

typedef unsigned long long ull;

// ---------------- f32x2 packed helpers ----------------
__device__ __forceinline__ ull pk2(float lo, float hi) {
    ull r; asm("mov.b64 %0, {%1, %2};" : "=l"(r) : "f"(lo), "f"(hi)); return r;
}
__device__ __forceinline__ ull dup2(float x) { return pk2(x, x); }
__device__ __forceinline__ void upk2(ull v, float& lo, float& hi) {
    asm("mov.b64 {%0, %1}, %2;" : "=f"(lo), "=f"(hi) : "l"(v));
}
__device__ __forceinline__ ull fma2(ull a, ull b, ull c) {
    ull d; asm("fma.rn.f32x2 %0, %1, %2, %3;" : "=l"(d) : "l"(a), "l"(b), "l"(c)); return d;
}
__device__ __forceinline__ ull abs2(ull a) { return a & 0x7fffffff7fffffffULL; }

// ---------------- scratch (device globals; no allocation allowed) ----------------
__device__ __align__(16) float g_Zj[BB*SS*DD];
__device__ __align__(16) float g_Zi[BB*SS*DD];
__device__ __align__(16) float g_probs[BB*SS*SS];     // 4 MB
__device__ __align__(16) float g_ctx[BB*SS*HH];       // 6 MB
__device__ __align__(16) float g_mhid[RR*HH];         // 6 MB

// ---------------- K1: Z projections ----------------
__global__ void proj_kernel(const float* __restrict__ Hj, const float* __restrict__ Hi,
                            const float* __restrict__ Wpj, const float* __restrict__ Wpi)
{
    int which = blockIdx.y;
    const float* Hsrc = which ? Hi : Hj;
    const float* W    = which ? Wpi : Wpj;
    float* Z          = which ? g_Zi : g_Zj;
    int row = blockIdx.x * 8 + threadIdx.y;
    int col = threadIdx.x;
    const float* h = Hsrc + (size_t)row * HH;
    float acc = 0.f;
    #pragma unroll 8
    for (int k = 0; k < HH; ++k)
        acc = fmaf(h[k], W[k*DD + col], acc);
    Z[row*DD + col] = acc;
}

// ---------------- K2: fused pairwise scores + softmax -> probs (f32x2) ----------------
// grid (SS, BB), block 256
__global__ void __launch_bounds__(256) pairwise_kernel(
        const float* __restrict__ Ws1, const float* __restrict__ bs1,
        const float* __restrict__ ws2, const float* __restrict__ bs2p,
        const int*   __restrict__ mask)
{
    extern __shared__ float smem[];
    float2* sPair  = (float2*)smem;                   // DD*MM float2 (4608 floats)
    float*  sZiT   = smem + 2*DD*MM;                  // DD*ZST (12336) transposed [d][q]
    float*  sLog   = sZiT + DD*ZST;                   // SS
    float*  sBias  = sLog + SS;                       // MM
    float*  sZj    = sBias + MM;                      // DD
    float*  sRed   = sZj + DD;                        // 32

    int b = blockIdx.y, p = blockIdx.x;
    int tid = threadIdx.x;
    int lane = tid & 31, warp = tid >> 5;

    if (tid < DD) sZj[tid] = g_Zj[((size_t)b*SS + p)*DD + tid];
    __syncthreads();

    // transpose Zi[b] into sZiT[d][q]
    {
        const float4* src = (const float4*)(g_Zi + (size_t)b*SS*DD);
        for (int i = tid; i < SS*DD/4; i += 256) {
            float4 v = src[i];
            int q = (4*i) / DD, d0 = (4*i) % DD;   // DD%4==0 -> never crosses a row
            sZiT[(d0+0)*ZST+q] = v.x;
            sZiT[(d0+1)*ZST+q] = v.y;
            sZiT[(d0+2)*ZST+q] = v.z;
            sZiT[(d0+3)*ZST+q] = v.w;
        }
    }
    // Wcomb[d,m] = W1i + Zj[p,d]*W1h ; paired with W1d
    for (int idx = tid; idx < DD*MM; idx += 256) {
        int d = idx / MM, m = idx - d*MM;
        float w1i = Ws1[(DD   + d)*MM + m];
        float w1h = Ws1[(2*DD + d)*MM + m];
        float w1d = Ws1[(3*DD + d)*MM + m];
        sPair[idx] = make_float2(fmaf(sZj[d], w1h, w1i), w1d);
    }
    if (tid < MM) {
        float acc = bs1[tid];
        #pragma unroll
        for (int d = 0; d < DD; ++d)
            acc = fmaf(sZj[d], Ws1[d*MM + tid], acc);
        sBias[tid] = acc;
    }
    __syncthreads();

    float zj[DD];
    #pragma unroll
    for (int d = 0; d < DD; ++d) zj[d] = sZj[d];

    int m0 = lane, m1 = lane + 32, m2 = lane + 64;
    float wsa = ws2[m0], wsb = ws2[m1], wsc = ws2[m2];
    ull bi0p = dup2(sBias[m0]), bi1p = dup2(sBias[m1]), bi2p = dup2(sBias[m2]);
    const ull NEG1 = dup2(-1.0f);
    float bsc = bs2p[0];
    const int* mrow = mask + b*SS;

    // each warp handles 8 q per iteration (4 packed pairs); 8 warps * 8 q * 8 iters = 512
    for (int it = 0; it < SS/64; ++it) {
        int qb = it*64 + warp*8;
        ull a00=bi0p,a01=bi1p,a02=bi2p, a10=bi0p,a11=bi1p,a12=bi2p;
        ull a20=bi0p,a21=bi1p,a22=bi2p, a30=bi0p,a31=bi1p,a32=bi2p;

        #pragma unroll
        for (int d = 0; d < DD; ++d) {
            const float2* zr = (const float2*)&sZiT[d*ZST + qb];   // broadcast loads
            float2 z01f = zr[0], z23f = zr[1], z45f = zr[2], z67f = zr[3];
            ull z01 = pk2(z01f.x, z01f.y);
            ull z23 = pk2(z23f.x, z23f.y);
            ull z45 = pk2(z45f.x, z45f.y);
            ull z67 = pk2(z67f.x, z67f.y);
            ull zjd = dup2(zj[d]);
            ull f01 = abs2(fma2(z01, NEG1, zjd));
            ull f23 = abs2(fma2(z23, NEG1, zjd));
            ull f45 = abs2(fma2(z45, NEG1, zjd));
            ull f67 = abs2(fma2(z67, NEG1, zjd));
            float2 w0 = sPair[d*MM + m0];
            float2 w1 = sPair[d*MM + m1];
            float2 w2 = sPair[d*MM + m2];
            ull wc0 = dup2(w0.x), wd0 = dup2(w0.y);
            ull wc1 = dup2(w1.x), wd1 = dup2(w1.y);
            ull wc2 = dup2(w2.x), wd2 = dup2(w2.y);
            a00 = fma2(z01, wc0, a00); a00 = fma2(f01, wd0, a00);
            a01 = fma2(z01, wc1, a01); a01 = fma2(f01, wd1, a01);
            a02 = fma2(z01, wc2, a02); a02 = fma2(f01, wd2, a02);
            a10 = fma2(z23, wc0, a10); a10 = fma2(f23, wd0, a10);
            a11 = fma2(z23, wc1, a11); a11 = fma2(f23, wd1, a11);
            a12 = fma2(z23, wc2, a12); a12 = fma2(f23, wd2, a12);
            a20 = fma2(z45, wc0, a20); a20 = fma2(f45, wd0, a20);
            a21 = fma2(z45, wc1, a21); a21 = fma2(f45, wd1, a21);
            a22 = fma2(z45, wc2, a22); a22 = fma2(f45, wd2, a22);
            a30 = fma2(z67, wc0, a30); a30 = fma2(f67, wd0, a30);
            a31 = fma2(z67, wc1, a31); a31 = fma2(f67, wd1, a31);
            a32 = fma2(z67, wc2, a32); a32 = fma2(f67, wd2, a32);
        }

        ull P0[4] = {a00, a10, a20, a30};
        ull P1[4] = {a01, a11, a21, a31};
        ull P2[4] = {a02, a12, a22, a32};
        #pragma unroll
        for (int qp = 0; qp < 4; ++qp) {
            float l0,h0,l1,h1,l2,h2;
            upk2(P0[qp], l0, h0); upk2(P1[qp], l1, h1); upk2(P2[qp], l2, h2);
            float sl = fmaxf(l0,0.f)*wsa + fmaxf(l1,0.f)*wsb + fmaxf(l2,0.f)*wsc;
            float sh = fmaxf(h0,0.f)*wsa + fmaxf(h1,0.f)*wsb + fmaxf(h2,0.f)*wsc;
            #pragma unroll
            for (int o = 16; o; o >>= 1) {
                sl += __shfl_xor_sync(0xffffffffu, sl, o);
                sh += __shfl_xor_sync(0xffffffffu, sh, o);
            }
            if (lane == 0) {
                int q0 = qb + 2*qp;
                float lg0 = sl + bsc, lg1 = sh + bsc;
                if (mrow[q0]   == 0) lg0 = -3.0e38f;
                if (mrow[q0+1] == 0) lg1 = -3.0e38f;
                sLog[q0]   = lg0;
                sLog[q0+1] = lg1;
            }
        }
    }
    __syncthreads();

    // block softmax over 512 logits
    float v = -3.4e38f;
    for (int i = tid; i < SS; i += 256) v = fmaxf(v, sLog[i]);
    #pragma unroll
    for (int o = 16; o; o >>= 1) v = fmaxf(v, __shfl_xor_sync(0xffffffffu, v, o));
    if (lane == 0) sRed[warp] = v;
    __syncthreads();
    float gmax = sRed[0];
    #pragma unroll
    for (int w = 1; w < 8; ++w) gmax = fmaxf(gmax, sRed[w]);
    __syncthreads();

    float ls = 0.f;
    for (int i = tid; i < SS; i += 256) {
        float e = expf(sLog[i] - gmax);
        sLog[i] = e;
        ls += e;
    }
    #pragma unroll
    for (int o = 16; o; o >>= 1) ls += __shfl_xor_sync(0xffffffffu, ls, o);
    if (lane == 0) sRed[warp] = ls;
    __syncthreads();
    float gsum = 0.f;
    #pragma unroll
    for (int w = 0; w < 8; ++w) gsum += sRed[w];
    float inv = 1.f / gsum;

    float* prow = g_probs + ((size_t)b*SS + p)*SS;
    for (int i = tid; i < SS; i += 256) prow[i] = sLog[i] * inv;
}

// ---------------- tiled SGEMM with f32x2 inner product ----------------
// C(MxN) = A(MxK) @ B(KxN). MODE 0: plain; 1: relu(+bias); 2: alpha*(+bias)
// FUSE: A is the virtual X = [ctx | Hj | ctx*Hj] built on the fly (K=2304)
template<int MODE, bool FUSE>
__global__ void __launch_bounds__(256) gemm_tile(
        const float* __restrict__ A, const float* __restrict__ Bm, float* __restrict__ C,
        int K, int N, size_t sA, size_t sB, size_t sC,
        const float* __restrict__ bias, const float* __restrict__ alphap,
        const float* __restrict__ Ctx, const float* __restrict__ HjP)
{
    A  += (size_t)blockIdx.z * sA;
    Bm += (size_t)blockIdx.z * sB;
    C  += (size_t)blockIdx.z * sC;

    __shared__ float As[16][64];
    __shared__ float Bs[16][64];

    int tid = threadIdx.x;
    int tx = tid & 15, ty = tid >> 4;
    int rowA = tid >> 2, cgA = tid & 3;     // A tile: 64 rows x 16 k
    int rowB = tid >> 4, cgB = tid & 15;    // B tile: 16 k x 64 cols

    int rowAglob = blockIdx.y*64 + rowA;
    const float* Aptr = A + (size_t)rowAglob*K + cgA*4;
    const float* Bptr = Bm + (size_t)rowB*N + blockIdx.x*64 + cgB*4;

    ull acc[4][2];
    #pragma unroll
    for (int i = 0; i < 4; ++i) { acc[i][0] = 0ULL; acc[i][1] = 0ULL; }

    for (int k0 = 0; k0 < K; k0 += 16) {
        float4 av;
        if (FUSE) {
            int kg = k0 + cgA*4;
            int region = (kg >= 2*HH) ? 2 : ((kg >= HH) ? 1 : 0);
            int kh = kg - region*HH;
            size_t off = (size_t)rowAglob*HH + kh;
            if (region == 0)      av = *(const float4*)(Ctx + off);
            else if (region == 1) av = *(const float4*)(HjP + off);
            else {
                float4 c = *(const float4*)(Ctx + off);
                float4 h = *(const float4*)(HjP + off);
                av = make_float4(c.x*h.x, c.y*h.y, c.z*h.z, c.w*h.w);
            }
        } else {
            av = *(const float4*)(Aptr + k0);
        }
        float4 bv = *(const float4*)(Bptr + (size_t)k0*N);
        As[cgA*4+0][rowA] = av.x;
        As[cgA*4+1][rowA] = av.y;
        As[cgA*4+2][rowA] = av.z;
        As[cgA*4+3][rowA] = av.w;
        *(float4*)&Bs[rowB][cgB*4] = bv;
        __syncthreads();
        #pragma unroll
        for (int kk = 0; kk < 16; ++kk) {
            float4 a  = *(const float4*)&As[kk][ty*4];
            float4 bq = *(const float4*)&Bs[kk][tx*4];
            ull b01 = pk2(bq.x, bq.y);
            ull b23 = pk2(bq.z, bq.w);
            ull a0 = dup2(a.x), a1 = dup2(a.y), a2 = dup2(a.z), a3 = dup2(a.w);
            acc[0][0] = fma2(a0, b01, acc[0][0]); acc[0][1] = fma2(a0, b23, acc[0][1]);
            acc[1][0] = fma2(a1, b01, acc[1][0]); acc[1][1] = fma2(a1, b23, acc[1][1]);
            acc[2][0] = fma2(a2, b01, acc[2][0]); acc[2][1] = fma2(a2, b23, acc[2][1]);
            acc[3][0] = fma2(a3, b01, acc[3][0]); acc[3][1] = fma2(a3, b23, acc[3][1]);
        }
        __syncthreads();
    }

    float al = (MODE == 2) ? *alphap : 1.f;
    int crow = blockIdx.y*64 + ty*4;
    int ccol = blockIdx.x*64 + tx*4;
    float bb[4] = {0.f, 0.f, 0.f, 0.f};
    if (MODE != 0) {
        #pragma unroll
        for (int j = 0; j < 4; ++j) bb[j] = bias[ccol + j];
    }
    #pragma unroll
    for (int i = 0; i < 4; ++i) {
        float v0, v1, v2, v3;
        upk2(acc[i][0], v0, v1);
        upk2(acc[i][1], v2, v3);
        v0 += bb[0]; v1 += bb[1]; v2 += bb[2]; v3 += bb[3];
        if (MODE == 1) { v0 = fmaxf(v0,0.f); v1 = fmaxf(v1,0.f); v2 = fmaxf(v2,0.f); v3 = fmaxf(v3,0.f); }
        if (MODE == 2) { v0 *= al; v1 *= al; v2 *= al; v3 *= al; }
        float4 o; o.x = v0; o.y = v1; o.z = v2; o.w = v3;
        *(float4*)&C[(size_t)(crow + i)*N + ccol] = o;
    }
}

// ---------------- launch ----------------
extern "C" void kernel_launch(void* const* d_in, const int* in_sizes, int n_in,
                              void* d_out, int out_size)
{
    const float* Hj   = (const float*)d_in[0];
    const float* Hi   = (const float*)d_in[1];
    const float* Wpj  = (const float*)d_in[2];
    const float* Wpi  = (const float*)d_in[3];
    const float* Ws1  = (const float*)d_in[4];
    const float* bs1  = (const float*)d_in[5];
    const float* ws2  = (const float*)d_in[6];
    const float* bs2  = (const float*)d_in[7];
    const float* Wv1  = (const float*)d_in[8];
    const float* bv1  = (const float*)d_in[9];
    const float* Wv2  = (const float*)d_in[10];
    const float* bv2  = (const float*)d_in[11];
    const float* alph = (const float*)d_in[12];
    const int*   amask= (const int*)d_in[13];
    float* out = (float*)d_out;

    float *pProbs, *pCtx, *pMhid;
    cudaGetSymbolAddress((void**)&pProbs, g_probs);
    cudaGetSymbolAddress((void**)&pCtx,   g_ctx);
    cudaGetSymbolAddress((void**)&pMhid,  g_mhid);

    // K1: projections
    proj_kernel<<<dim3(RR/8, 2), dim3(24, 8)>>>(Hj, Hi, Wpj, Wpi);

    // K2: pairwise + softmax
    const size_t smemPW = (size_t)(2*DD*MM + DD*ZST + SS + MM + DD + 32) * sizeof(float);
    cudaFuncSetAttribute(pairwise_kernel, cudaFuncAttributeMaxDynamicSharedMemorySize, (int)smemPW);
    pairwise_kernel<<<dim3(SS, BB), 256, smemPW>>>(Ws1, bs1, ws2, bs2, amask);

    // K3: ctx = probs @ H_i   (batched: M=512, K=512, N=768)
    gemm_tile<0, false><<<dim3(HH/64, SS/64, BB), 256>>>(
        pProbs, Hi, pCtx, SS, HH,
        (size_t)SS*SS, (size_t)SS*HH, (size_t)SS*HH, nullptr, nullptr, nullptr, nullptr);

    // K4: mhid = relu(X @ Wv1 + bv1), X built on the fly (M=2048, K=2304, N=768)
    gemm_tile<1, true><<<dim3(HH/64, RR/64, 1), 256>>>(
        nullptr, Wv1, pMhid, KX, HH, 0, 0, 0, bv1, nullptr, pCtx, Hj);

    // K5: out = alpha * (mhid @ Wv2 + bv2)  (M=2048, K=768, N=768)
    gemm_tile<2, false><<<dim3(HH/64, RR/64, 1), 256>>>(
        pMhid, Wv2, out, HH, HH, 0, 0, 0, bv2, alph, nullptr, nullptr);
}